// round 7
// baseline (speedup 1.0000x reference)
#include <cuda_runtime.h>
#include <cuda_fp16.h>
#include <cuda_fp8.h>
#include <cstdint>
#include <cfloat>
#include <math.h>

#define Bn 2
#define Ln 4096
#define Hn 8
#define Dn 64
#define NTOP 45
#define NSAMP 45
#define NCAND 160
#define BHn (Bn*Hn)
#define SPLITS 32
#define CHUNK (Ln/SPLITS)
#define SUB 64

// ---------------- device scratch ----------------
__device__ float    g_M[BHn * Ln];
__device__ int      g_top[BHn * NTOP];
__device__ unsigned g_anyodd = 0u;     // OR-accumulated; deterministic across replays
__device__ unsigned g_Kf8[(size_t)Bn*Ln*Hn*Dn/4];   // e4m3 copy of K, 4 MB
__device__ float    g_pl [BHn * NTOP * SPLITS];
__device__ float    g_pacc[(size_t)BHn * NTOP * SPLITS * Dn];

// ---------------- K -> fp8 copy + index dtype detect (fused) ----------------
__global__ __launch_bounds__(256) void k_init(const float* __restrict__ k,
                                              const unsigned* __restrict__ raw) {
    int i = blockIdx.x * 256 + threadIdx.x;          // handles 8 floats
    float4 f0 = ((const float4*)k)[2*i];
    float4 f1 = ((const float4*)k)[2*i+1];
    unsigned s0 = __nv_cvt_float2_to_fp8x2(make_float2(f0.x,f0.y), __NV_SATFINITE, __NV_E4M3);
    unsigned s1 = __nv_cvt_float2_to_fp8x2(make_float2(f0.z,f0.w), __NV_SATFINITE, __NV_E4M3);
    unsigned s2 = __nv_cvt_float2_to_fp8x2(make_float2(f1.x,f1.y), __NV_SATFINITE, __NV_E4M3);
    unsigned s3 = __nv_cvt_float2_to_fp8x2(make_float2(f1.z,f1.w), __NV_SATFINITE, __NV_E4M3);
    *(uint2*)&g_Kf8[2*i] = make_uint2(s0 | (s1 << 16), s2 | (s3 << 16));

    if (blockIdx.x < 90) {
        unsigned v = 0;
        for (int j = 1 + 2*i; j < Ln*NSAMP; j += 2*90*256) v |= raw[j];
        #pragma unroll
        for (int o = 16; o; o >>= 1) v |= __shfl_xor_sync(0xffffffffu, v, o);
        if ((threadIdx.x & 31) == 0 && v) atomicOr(&g_anyodd, v);
    }
}

// ---------------- stage 1: fp8 screen, one warp = (b,l) x all 8 heads ----------------
// Per sample: ONE LDG.128 (32 lanes x 16B = 512B = fp8 row for all heads).
// Lane: head = lane>>2, dims quad*16..+16. half2 FMA chain, 2-shfl quad reduce.
__global__ __launch_bounds__(256) void k_scoreM(const float* __restrict__ q,
                                                const unsigned* __restrict__ raw) {
    int w    = (blockIdx.x * 256 + threadIdx.x) >> 5;   // < Bn*Ln
    int lane = threadIdx.x & 31;
    int head = lane >> 2;
    int quad = lane & 3;
    int b = w / Ln, l = w % Ln;

    const float4* qp = (const float4*)(q + (((size_t)b*Ln + l)*Hn + head)*Dn + quad*16);
    half2 qh[8];
    #pragma unroll
    for (int j = 0; j < 4; j++) {
        float4 f = qp[j];
        qh[2*j]   = __floats2half2_rn(f.x, f.y);
        qh[2*j+1] = __floats2half2_rn(f.z, f.w);
    }

    int sh = (g_anyodd == 0u) ? 1 : 0;
    const unsigned* ip = raw + ((size_t)(l * NSAMP) << sh);
    int i0 = (int)ip[(unsigned)lane << sh];
    int i1 = (lane < NSAMP - 32) ? (int)ip[(unsigned)(32 + lane) << sh] : 0;

    const uint4* kb = (const uint4*)g_Kf8 + (size_t)b * (Ln * 32);

    float mx = -FLT_MAX, sm = 0.f;
    #pragma unroll 9
    for (int s = 0; s < NSAMP; s++) {
        int id = __shfl_sync(0xffffffffu, (s < 32) ? i0 : i1, s & 31);
        uint4 kw = __ldg(kb + (id << 5) + lane);
        half2 acc;
        {
            __half2_raw h;
            h = __nv_cvt_fp8x2_to_halfraw2((__nv_fp8x2_storage_t)(kw.x & 0xffff), __NV_E4M3);
            acc = __hmul2(*(half2*)&h, qh[0]);
            h = __nv_cvt_fp8x2_to_halfraw2((__nv_fp8x2_storage_t)(kw.x >> 16), __NV_E4M3);
            acc = __hfma2(*(half2*)&h, qh[1], acc);
            h = __nv_cvt_fp8x2_to_halfraw2((__nv_fp8x2_storage_t)(kw.y & 0xffff), __NV_E4M3);
            acc = __hfma2(*(half2*)&h, qh[2], acc);
            h = __nv_cvt_fp8x2_to_halfraw2((__nv_fp8x2_storage_t)(kw.y >> 16), __NV_E4M3);
            acc = __hfma2(*(half2*)&h, qh[3], acc);
            h = __nv_cvt_fp8x2_to_halfraw2((__nv_fp8x2_storage_t)(kw.z & 0xffff), __NV_E4M3);
            acc = __hfma2(*(half2*)&h, qh[4], acc);
            h = __nv_cvt_fp8x2_to_halfraw2((__nv_fp8x2_storage_t)(kw.z >> 16), __NV_E4M3);
            acc = __hfma2(*(half2*)&h, qh[5], acc);
            h = __nv_cvt_fp8x2_to_halfraw2((__nv_fp8x2_storage_t)(kw.w & 0xffff), __NV_E4M3);
            acc = __hfma2(*(half2*)&h, qh[6], acc);
            h = __nv_cvt_fp8x2_to_halfraw2((__nv_fp8x2_storage_t)(kw.w >> 16), __NV_E4M3);
            acc = __hfma2(*(half2*)&h, qh[7], acc);
        }
        float d = __low2float(acc) + __high2float(acc);
        d += __shfl_xor_sync(0xffffffffu, d, 1);
        d += __shfl_xor_sync(0xffffffffu, d, 2);
        mx = fmaxf(mx, d);
        sm += d;
    }
    if (quad == 0)
        g_M[(b*Hn + head)*Ln + l] = mx - sm * (1.0f / (float)Ln);
}

// ---------------- stage 2: candidates + exact rescore + exact top-45 ----------------
__global__ __launch_bounds__(1024) void k_select(const float* __restrict__ q,
                                                 const float* __restrict__ k,
                                                 const unsigned* __restrict__ raw) {
    int bh  = blockIdx.x;
    int b = bh / Hn, h = bh % Hn;
    int tid = threadIdx.x;
    int lane = tid & 31, warp = tid >> 5;

    __shared__ int bins[256];
    __shared__ int ssum[256];
    __shared__ int s_sel, s_need, s_out;
    __shared__ int s_cand[NCAND + 64];         // overflow slack for ties
    __shared__ float s_Mex[NCAND];
    __shared__ unsigned long long comp[NCAND];

    // ---- phase A: approx top-NCAND via radix-256 select ----
    unsigned r[4];
    #pragma unroll
    for (int i = 0; i < 4; i++) {
        unsigned u = __float_as_uint(g_M[bh*Ln + tid + i*1024]);
        r[i] = (u & 0x80000000u) ? ~u : (u | 0x80000000u);
    }

    unsigned prefix = 0;
    int need = NCAND;
    #pragma unroll
    for (int p = 0; p < 4; p++) {
        int shift = 24 - 8*p;
        unsigned pmask = (p == 0) ? 0u : (0xFFFFFFFFu << (32 - 8*p));
        if (tid < 256) bins[tid] = 0;
        __syncthreads();
        #pragma unroll
        for (int i = 0; i < 4; i++)
            if ((r[i] & pmask) == prefix)
                atomicAdd(&bins[(r[i] >> shift) & 255], 1);
        __syncthreads();
        if (tid < 32) {
            int x[8], loc = 0;
            #pragma unroll
            for (int j = 0; j < 8; j++) { x[j] = bins[lane*8 + j]; loc += x[j]; }
            int suf = loc;
            #pragma unroll
            for (int o = 1; o < 32; o <<= 1) {
                int t = __shfl_down_sync(0xffffffffu, suf, o);
                if (lane + o < 32) suf += t;
            }
            int run = suf - loc;
            #pragma unroll
            for (int j = 7; j >= 0; j--) { run += x[j]; ssum[lane*8 + j] = run; }
        }
        __syncthreads();
        if (tid < 256) {
            int above = (tid < 255) ? ssum[tid + 1] : 0;
            if (ssum[tid] >= need && above < need) { s_sel = tid; s_need = need - above; }
        }
        __syncthreads();
        prefix |= ((unsigned)s_sel) << shift;
        need    = s_need;
        __syncthreads();
    }
    unsigned T = prefix;

    if (tid == 0) s_out = 0;
    __syncthreads();
    #pragma unroll
    for (int i = 0; i < 4; i++)
        if (r[i] > T) {
            int p = atomicAdd(&s_out, 1);
            s_cand[p] = tid + i*1024;
        }
    __syncthreads();
    #pragma unroll
    for (int i = 0; i < 4; i++)
        if (r[i] == T) {
            int p = atomicAdd(&s_out, 1);
            if (p < NCAND) s_cand[p] = tid + i*1024;
        }
    __syncthreads();

    // ---- phase B: exact fp32 rescore (warp per candidate, 5 rounds) ----
    int sh = (g_anyodd == 0u) ? 1 : 0;
    #pragma unroll
    for (int rd = 0; rd < NCAND/32; rd++) {
        int c = rd*32 + warp;
        int l = s_cand[c];
        const float2 qv = *(const float2*)(q + (((size_t)b*Ln + l)*Hn + h)*Dn + 2*lane);
        const unsigned* ip = raw + ((size_t)(l * NSAMP) << sh);
        int i0 = (int)ip[(unsigned)lane << sh];
        int i1 = (lane < NSAMP - 32) ? (int)ip[(unsigned)(32 + lane) << sh] : 0;

        float mx = -FLT_MAX, sm = 0.f;
        #pragma unroll 9
        for (int s = 0; s < NSAMP; s++) {
            int id = __shfl_sync(0xffffffffu, (s < 32) ? i0 : i1, s & 31);
            float2 kv = *(const float2*)(k + (((size_t)b*Ln + id)*Hn + h)*Dn + 2*lane);
            float d2 = qv.x*kv.x + qv.y*kv.y;
            #pragma unroll
            for (int o = 16; o; o >>= 1) d2 += __shfl_xor_sync(0xffffffffu, d2, o);
            mx = fmaxf(mx, d2);
            sm += d2;
        }
        if (lane == 0) s_Mex[c] = mx - sm * (1.0f / (float)Ln);
    }
    __syncthreads();

    // ---- phase C: exact top-45 of NCAND (jax tie-break: value desc, index asc) ----
    if (tid < NCAND) {
        int idx = s_cand[tid];
        unsigned u = __float_as_uint(s_Mex[tid]);
        u = (u & 0x80000000u) ? ~u : (u | 0x80000000u);
        comp[tid] = ((unsigned long long)u << 32) | (unsigned)(Ln - 1 - idx);
    }
    __syncthreads();
    if (tid < NCAND) {
        unsigned long long mine = comp[tid];
        int rank = 0;
        #pragma unroll 16
        for (int j = 0; j < NCAND; j++) rank += (comp[j] > mine);
        if (rank < NTOP) g_top[bh*NTOP + rank] = s_cand[tid];
    }
}

// ---------------- stage 3: split-KV attention partials ----------------
__global__ __launch_bounds__(256) void k_attn(const float* __restrict__ q,
                                              const float* __restrict__ k,
                                              const float* __restrict__ v) {
    int split = blockIdx.x;
    int bh    = blockIdx.y;
    int b = bh / Hn, h = bh % Hn;
    int tid = threadIdx.x, warp = tid >> 5, lane = tid & 31;

    __shared__ __align__(16) float2 Kt2[32 * 65];   // reused as ps[8][64][8]
    __shared__ float2 Vs2[64 * 32];
    __shared__ float  Qs[48 * 64];
    float* ps = (float*)Kt2;

    for (int e = tid; e < 48 * (Dn/4); e += 256) {
        int u  = e >> 4;
        int c4 = e & 15;
        float4 qf = make_float4(0.f, 0.f, 0.f, 0.f);
        if (u < NTOP) {
            int lq = g_top[bh*NTOP + u];
            qf = *((const float4*)(q + (((size_t)b*Ln + lq)*Hn + h)*Dn) + c4);
        }
        ((float4*)Qs)[e] = qf;
    }

    int nq = 5 + (warp < (NTOP % 8) ? 1 : 0);
    float2 acc[6];
    float  lt[6];
    #pragma unroll
    for (int i = 0; i < 6; i++) { acc[i] = make_float2(0.f, 0.f); lt[i] = 0.f; }

    for (int c = 0; c < 2; c++) {
        if (c) __syncthreads();
        int base_l = split * CHUNK + c * SUB;
        for (int e = tid; e < SUB * (Dn/4); e += 256) {
            int row  = e >> 4;
            int col4 = e & 15;
            size_t g = (((size_t)b*Ln + base_l + row)*Hn + h)*Dn;
            float4 kf = *((const float4*)(k + g) + col4);
            float4 vf = *((const float4*)(v + g) + col4);
            ((float4*)Vs2)[e] = vf;
            int dp0 = col4 * 2;
            Kt2[dp0*65 + row]     = make_float2(kf.x, kf.y);
            Kt2[(dp0+1)*65 + row] = make_float2(kf.z, kf.w);
        }
        __syncthreads();

        float s0[6], s1[6];
        #pragma unroll
        for (int i = 0; i < 6; i++) { s0[i] = 0.f; s1[i] = 0.f; }
        #pragma unroll
        for (int dp = 0; dp < 32; dp++) {
            float2 k0 = Kt2[dp*65 + lane];
            float2 k1 = Kt2[dp*65 + 32 + lane];
            #pragma unroll
            for (int i = 0; i < 6; i++) {
                float2 qd = *(const float2*)&Qs[(warp + 8*i)*64 + 2*dp];
                s0[i] += qd.x*k0.x + qd.y*k0.y;
                s1[i] += qd.x*k1.x + qd.y*k1.y;
            }
        }
        __syncthreads();

        const float scale = 0.125f;
        float* pw = ps + warp * 512;
        #pragma unroll
        for (int i = 0; i < 6; i++) {
            float p0 = __expf(s0[i] * scale);
            float p1 = __expf(s1[i] * scale);
            pw[lane*8 + i]      = p0;
            pw[(lane+32)*8 + i] = p1;
            float ls = p0 + p1;
            #pragma unroll
            for (int o = 16; o; o >>= 1) ls += __shfl_xor_sync(0xffffffffu, ls, o);
            lt[i] += ls;
        }
        __syncwarp();

        #pragma unroll 4
        for (int j = 0; j < SUB; j++) {
            float2 vv = Vs2[j*32 + lane];
            float4 pA = *(const float4*)&pw[j*8];
            float2 pB = *(const float2*)&pw[j*8 + 4];
            acc[0].x += pA.x*vv.x; acc[0].y += pA.x*vv.y;
            acc[1].x += pA.y*vv.x; acc[1].y += pA.y*vv.y;
            acc[2].x += pA.z*vv.x; acc[2].y += pA.z*vv.y;
            acc[3].x += pA.w*vv.x; acc[3].y += pA.w*vv.y;
            acc[4].x += pB.x*vv.x; acc[4].y += pB.x*vv.y;
            acc[5].x += pB.y*vv.x; acc[5].y += pB.y*vv.y;
        }
    }

    for (int i = 0; i < nq; i++) {
        int u = warp + 8*i;
        size_t pidx = (size_t)(bh*NTOP + u)*SPLITS + split;
        if (lane == 0) g_pl[pidx] = lt[i];
        *(float2*)(g_pacc + pidx*Dn + 2*lane) = acc[i];
    }
}

// ---------------- stage 4: combine splits + scatter ----------------
__global__ __launch_bounds__(256) void k_combine(float* __restrict__ out) {
    int gi = blockIdx.x;
    int bh = gi / NTOP, u = gi % NTOP;
    int b = bh / Hn, h = bh % Hn;
    int tid = threadIdx.x;
    int grp = tid >> 6, d = tid & 63;

    __shared__ float lsh[SPLITS];
    __shared__ float part[4][64];

    if (tid < SPLITS) lsh[tid] = g_pl[(size_t)gi*SPLITS + tid];
    __syncthreads();

    float a = 0.f;
    #pragma unroll
    for (int s8 = 0; s8 < 8; s8++)
        a += g_pacc[((size_t)gi*SPLITS + grp*8 + s8)*Dn + d];
    part[grp][d] = a;
    __syncthreads();

    if (grp == 0) {
        float den = 0.f;
        #pragma unroll
        for (int s = 0; s < SPLITS; s++) den += lsh[s];
        float tot = part[0][d] + part[1][d] + part[2][d] + part[3][d];
        int lq = g_top[bh*NTOP + u];
        out[(((size_t)b*Ln + lq)*Hn + h)*Dn + d] = tot / den;
    }
}

// ---------------- launch ----------------
extern "C" void kernel_launch(void* const* d_in, const int* in_sizes, int n_in,
                              void* d_out, int out_size) {
    const float* q = (const float*)d_in[0];
    const float* k = (const float*)d_in[1];
    const float* v = (const float*)d_in[2];
    const unsigned* idxraw = (const unsigned*)d_in[4];
    float* out = (float*)d_out;

    cudaMemsetAsync(d_out, 0, (size_t)out_size * sizeof(float));

    k_init   <<<(Bn*Ln*Hn*Dn/8)/256, 256>>>(k, idxraw);  // #1
    k_scoreM <<<(Bn*Ln)/8, 256>>>(q, idxraw);            // #2
    k_select <<<BHn, 1024>>>(q, k, idxraw);              // #3
    dim3 g3(SPLITS, BHn);
    k_attn   <<<g3, 256>>>(q, k, v);                     // #4 (ncu target)
    k_combine<<<BHn*NTOP, 256>>>(out);                   // #5
}